// round 3
// baseline (speedup 1.0000x reference)
#include <cuda_runtime.h>

#define PVOL   29791          // 31^3
#define MROWS  119164         // 4 * 31^3
#define D1     512
#define KK     128
#define BM     128
#define BN     128
#define COLIT  2              // column blocks per CTA

// XOR swizzle on the m index: kills 2-way quad conflicts for stride-8 LDS.128
#define SW(m) ((m) ^ ((((m) >> 5) & 1) << 2))

__device__ __forceinline__ unsigned long long pack2(float lo, float hi) {
    unsigned long long r;
    asm("mov.b64 %0, {%1, %2};" : "=l"(r) : "f"(lo), "f"(hi));
    return r;
}
__device__ __forceinline__ void unpack2(unsigned long long v, float& lo, float& hi) {
    asm("mov.b64 {%0, %1}, %2;" : "=f"(lo), "=f"(hi) : "l"(v));
}
__device__ __forceinline__ void ffma2(unsigned long long& acc,
                                      unsigned long long a, unsigned long long b) {
    asm("fma.rn.f32x2 %0, %1, %2, %0;" : "+l"(acc) : "l"(a), "l"(b));
}

__global__ __launch_bounds__(256, 1)
void gk_kernel(const float* __restrict__ x, const float* __restrict__ w,
               float* __restrict__ out) {
    extern __shared__ float sm[];
    float* sA   = sm;                       // [KK][128] swizzled in m
    float* sB   = sm + KK * 128;            // [KK][128]
    float* st   = sm + 2 * KK * 128;        // [BN][128] stage, swizzled in m
    float* ysqp = sm + 3 * KK * 128;        // [2][128] partial ||y||^2
    float* wsqp = ysqp + 256;               // [2][128] partial ||w||^2

    const int tid  = threadIdx.x;
    const int row0 = blockIdx.x * BM;

    // ---------------- gather A (once) + ||y||^2 partials --------------------
    {
        const int m   = tid & 127;
        const int kw  = tid >> 7;            // innermost patch bit
        const int row = row0 + m;
        float s = 0.0f;
        if (row < MROWS) {
            const int n   = row / PVOL;
            const int p   = row - n * PVOL;
            const int d   = p / 961;
            const int rem = p - d * 961;
            const int h   = rem / 31;
            const int wx  = rem - h * 31;
            const long base = (long)n * 524288 + d * 1024 + h * 32 + wx + kw;
            const int ms = SW(m);
            #pragma unroll 8
            for (int it = 0; it < 64; ++it) {
                const int c  = it >> 2;
                const int kd = (it >> 1) & 1;
                const int kh = it & 1;
                const float v = x[base + (long)c * 32768 + kd * 1024 + kh * 32];
                sA[(it * 2 + kw) * 128 + ms] = v;
                s = fmaf(v, v, s);
            }
        } else {
            const int ms = SW(m);
            #pragma unroll 8
            for (int it = 0; it < 64; ++it)
                sA[(it * 2 + kw) * 128 + ms] = 0.0f;
        }
        ysqp[kw * 128 + m] = s;
    }
    __syncthreads();

    const int tx = tid & 15;
    const int ty = tid >> 4;
    const int tm = tx * 8;
    const int tn = ty * 8;

    float ys[8];
    #pragma unroll
    for (int i = 0; i < 8; ++i) ys[i] = ysqp[tm + i] + ysqp[128 + tm + i];

    for (int iter = 0; iter < COLIT; ++iter) {
        const int col0 = (blockIdx.y * COLIT + iter) * BN;

        // ------------- fill B (conflict-free) + ||w||^2 partials ------------
        {
            const int nn   = tid & 127;
            const int half = tid >> 7;
            float s = 0.0f;
            #pragma unroll
            for (int it = 0; it < 16; ++it) {
                const int k4 = half + it * 2;          // quad of k values
                const float4 v = *(const float4*)&w[(long)(col0 + nn) * KK + k4 * 4];
                sB[(k4 * 4 + 0) * 128 + nn] = v.x;
                sB[(k4 * 4 + 1) * 128 + nn] = v.y;
                sB[(k4 * 4 + 2) * 128 + nn] = v.z;
                sB[(k4 * 4 + 3) * 128 + nn] = v.w;
                s = fmaf(v.x, v.x, s);
                s = fmaf(v.y, v.y, s);
                s = fmaf(v.z, v.z, s);
                s = fmaf(v.w, v.w, s);
            }
            wsqp[half * 128 + nn] = s;
        }
        __syncthreads();

        // ------------- GEMM: 8x8 micro-tile, packed f32x2 FMAs --------------
        unsigned long long acc[4][8];
        #pragma unroll
        for (int i = 0; i < 4; ++i)
            #pragma unroll
            for (int j = 0; j < 8; ++j) acc[i][j] = 0ull;

        const int tms0 = SW(tm);        // swizzled offsets (constant per thread)
        const int tms1 = SW(tm + 4);

        #pragma unroll 4
        for (int k = 0; k < KK; ++k) {
            const float4 a0 = *(const float4*)&sA[k * 128 + tms0];
            const float4 a1 = *(const float4*)&sA[k * 128 + tms1];
            const float4 b0 = *(const float4*)&sB[k * 128 + tn];
            const float4 b1 = *(const float4*)&sB[k * 128 + tn + 4];

            unsigned long long A[4];
            A[0] = pack2(a0.x, a0.y);
            A[1] = pack2(a0.z, a0.w);
            A[2] = pack2(a1.x, a1.y);
            A[3] = pack2(a1.z, a1.w);

            unsigned long long B[8];
            B[0] = pack2(b0.x, b0.x);
            B[1] = pack2(b0.y, b0.y);
            B[2] = pack2(b0.z, b0.z);
            B[3] = pack2(b0.w, b0.w);
            B[4] = pack2(b1.x, b1.x);
            B[5] = pack2(b1.y, b1.y);
            B[6] = pack2(b1.z, b1.z);
            B[7] = pack2(b1.w, b1.w);

            #pragma unroll
            for (int i = 0; i < 4; ++i)
                #pragma unroll
                for (int j = 0; j < 8; ++j)
                    ffma2(acc[i][j], A[i], B[j]);
        }

        float ws[8];
        #pragma unroll
        for (int j = 0; j < 8; ++j) ws[j] = wsqp[tn + j] + wsqp[128 + tn + j];

        // ------------- epilogue: exp -> swizzled stage ----------------------
        #pragma unroll
        for (int i = 0; i < 4; ++i) {
            #pragma unroll
            for (int j = 0; j < 8; ++j) {
                float v0, v1;
                unpack2(acc[i][j], v0, v1);
                const float e0 = __expf(fmaf(2.0f, v0, -(ys[2 * i]     + ws[j])));
                const float e1 = __expf(fmaf(2.0f, v1, -(ys[2 * i + 1] + ws[j])));
                *(float2*)&st[(tn + j) * 128 + SW(tm + 2 * i)] = make_float2(e0, e1);
            }
        }
        __syncthreads();

        // ------------- coalesced global stores ------------------------------
        #pragma unroll 4
        for (int l = 0; l < 64; ++l) {
            const int e   = tid + l * 256;
            const int col = e >> 7;
            const int m   = e & 127;
            const int row = row0 + m;
            if (row < MROWS) {
                const int n = row / PVOL;
                const int p = row - n * PVOL;
                out[(long)(n * D1 + col0 + col) * PVOL + p] = st[col * 128 + SW(m)];
            }
        }
        if (iter + 1 < COLIT) __syncthreads();   // protect sB/st for next iter
    }
}

extern "C" void kernel_launch(void* const* d_in, const int* in_sizes, int n_in,
                              void* d_out, int out_size) {
    const float* x = (const float*)d_in[0];
    const float* w = (const float*)d_in[1];
    float* out = (float*)d_out;

    const int smem_bytes = (3 * KK * 128 + 512) * (int)sizeof(float); // 198,656
    cudaFuncSetAttribute(gk_kernel, cudaFuncAttributeMaxDynamicSharedMemorySize,
                         smem_bytes);

    dim3 grid((MROWS + BM - 1) / BM, D1 / (BN * COLIT));  // (931, 2)
    gk_kernel<<<grid, 256, smem_bytes>>>(x, w, out);
}

// round 4
// speedup vs baseline: 1.0024x; 1.0024x over previous
#include <cuda_runtime.h>

#define PVOL   29791          // 31^3
#define MROWS  119164         // 4 * 31^3
#define D1     512
#define KK     128
#define BM     128
#define BN     128
#define COLIT  2              // column blocks per CTA

// XOR swizzle on the m index: kills 2-way quad conflicts for stride-8 LDS.128
#define SW(m) ((m) ^ ((((m) >> 5) & 1) << 2))

__device__ __forceinline__ unsigned long long pack2(float lo, float hi) {
    unsigned long long r;
    asm("mov.b64 %0, {%1, %2};" : "=l"(r) : "f"(lo), "f"(hi));
    return r;
}
__device__ __forceinline__ void unpack2(unsigned long long v, float& lo, float& hi) {
    asm("mov.b64 {%0, %1}, %2;" : "=f"(lo), "=f"(hi) : "l"(v));
}
__device__ __forceinline__ void ffma2(unsigned long long& acc,
                                      unsigned long long a, unsigned long long b) {
    asm("fma.rn.f32x2 %0, %1, %2, %0;" : "+l"(acc) : "l"(a), "l"(b));
}

__global__ __launch_bounds__(256, 1)
void gk_kernel(const float* __restrict__ x, const float* __restrict__ w,
               float* __restrict__ out) {
    extern __shared__ float sm[];
    float* sA   = sm;                       // [KK][128] swizzled in m
    float* sB   = sm + KK * 128;            // [KK][128]
    float* st   = sm + 2 * KK * 128;        // [BN][128] stage, swizzled in m
    float* ysqp = sm + 3 * KK * 128;        // [2][128] partial ||y||^2
    float* wsqp = ysqp + 256;               // [2][128] partial ||w||^2

    const int tid  = threadIdx.x;
    const int row0 = blockIdx.x * BM;

    // ---------------- gather A (once) + ||y||^2 partials --------------------
    {
        const int m   = tid & 127;
        const int kw  = tid >> 7;            // innermost patch bit
        const int row = row0 + m;
        float s = 0.0f;
        if (row < MROWS) {
            const int n   = row / PVOL;
            const int p   = row - n * PVOL;
            const int d   = p / 961;
            const int rem = p - d * 961;
            const int h   = rem / 31;
            const int wx  = rem - h * 31;
            const long base = (long)n * 524288 + d * 1024 + h * 32 + wx + kw;
            const int ms = SW(m);
            #pragma unroll 8
            for (int it = 0; it < 64; ++it) {
                const int c  = it >> 2;
                const int kd = (it >> 1) & 1;
                const int kh = it & 1;
                const float v = x[base + (long)c * 32768 + kd * 1024 + kh * 32];
                sA[(it * 2 + kw) * 128 + ms] = v;
                s = fmaf(v, v, s);
            }
        } else {
            const int ms = SW(m);
            #pragma unroll 8
            for (int it = 0; it < 64; ++it)
                sA[(it * 2 + kw) * 128 + ms] = 0.0f;
        }
        ysqp[kw * 128 + m] = s;
    }
    __syncthreads();

    const int tx = tid & 15;
    const int ty = tid >> 4;
    const int tm = tx * 8;
    const int tn = ty * 8;

    float ys[8];
    #pragma unroll
    for (int i = 0; i < 8; ++i) ys[i] = ysqp[tm + i] + ysqp[128 + tm + i];

    for (int iter = 0; iter < COLIT; ++iter) {
        const int col0 = (blockIdx.y * COLIT + iter) * BN;

        // ------------- fill B (conflict-free) + ||w||^2 partials ------------
        {
            const int nn   = tid & 127;
            const int half = tid >> 7;
            float s = 0.0f;
            #pragma unroll
            for (int it = 0; it < 16; ++it) {
                const int k4 = half + it * 2;          // quad of k values
                const float4 v = *(const float4*)&w[(long)(col0 + nn) * KK + k4 * 4];
                sB[(k4 * 4 + 0) * 128 + nn] = v.x;
                sB[(k4 * 4 + 1) * 128 + nn] = v.y;
                sB[(k4 * 4 + 2) * 128 + nn] = v.z;
                sB[(k4 * 4 + 3) * 128 + nn] = v.w;
                s = fmaf(v.x, v.x, s);
                s = fmaf(v.y, v.y, s);
                s = fmaf(v.z, v.z, s);
                s = fmaf(v.w, v.w, s);
            }
            wsqp[half * 128 + nn] = s;
        }
        __syncthreads();

        // ------------- GEMM: 8x8 micro-tile, packed f32x2 FMAs --------------
        unsigned long long acc[4][8];
        #pragma unroll
        for (int i = 0; i < 4; ++i)
            #pragma unroll
            for (int j = 0; j < 8; ++j) acc[i][j] = 0ull;

        const int tms0 = SW(tm);        // swizzled offsets (constant per thread)
        const int tms1 = SW(tm + 4);

        #pragma unroll 4
        for (int k = 0; k < KK; ++k) {
            const float4 a0 = *(const float4*)&sA[k * 128 + tms0];
            const float4 a1 = *(const float4*)&sA[k * 128 + tms1];
            const float4 b0 = *(const float4*)&sB[k * 128 + tn];
            const float4 b1 = *(const float4*)&sB[k * 128 + tn + 4];

            unsigned long long A[4];
            A[0] = pack2(a0.x, a0.y);
            A[1] = pack2(a0.z, a0.w);
            A[2] = pack2(a1.x, a1.y);
            A[3] = pack2(a1.z, a1.w);

            unsigned long long B[8];
            B[0] = pack2(b0.x, b0.x);
            B[1] = pack2(b0.y, b0.y);
            B[2] = pack2(b0.z, b0.z);
            B[3] = pack2(b0.w, b0.w);
            B[4] = pack2(b1.x, b1.x);
            B[5] = pack2(b1.y, b1.y);
            B[6] = pack2(b1.z, b1.z);
            B[7] = pack2(b1.w, b1.w);

            #pragma unroll
            for (int i = 0; i < 4; ++i)
                #pragma unroll
                for (int j = 0; j < 8; ++j)
                    ffma2(acc[i][j], A[i], B[j]);
        }

        float ws[8];
        #pragma unroll
        for (int j = 0; j < 8; ++j) ws[j] = wsqp[tn + j] + wsqp[128 + tn + j];

        // ------------- epilogue: exp -> swizzled stage ----------------------
        #pragma unroll
        for (int i = 0; i < 4; ++i) {
            #pragma unroll
            for (int j = 0; j < 8; ++j) {
                float v0, v1;
                unpack2(acc[i][j], v0, v1);
                const float e0 = __expf(fmaf(2.0f, v0, -(ys[2 * i]     + ws[j])));
                const float e1 = __expf(fmaf(2.0f, v1, -(ys[2 * i + 1] + ws[j])));
                *(float2*)&st[(tn + j) * 128 + SW(tm + 2 * i)] = make_float2(e0, e1);
            }
        }
        __syncthreads();

        // ------------- coalesced global stores ------------------------------
        #pragma unroll 4
        for (int l = 0; l < 64; ++l) {
            const int e   = tid + l * 256;
            const int col = e >> 7;
            const int m   = e & 127;
            const int row = row0 + m;
            if (row < MROWS) {
                const int n = row / PVOL;
                const int p = row - n * PVOL;
                out[(long)(n * D1 + col0 + col) * PVOL + p] = st[col * 128 + SW(m)];
            }
        }
        if (iter + 1 < COLIT) __syncthreads();   // protect sB/st for next iter
    }
}

extern "C" void kernel_launch(void* const* d_in, const int* in_sizes, int n_in,
                              void* d_out, int out_size) {
    const float* x = (const float*)d_in[0];
    const float* w = (const float*)d_in[1];
    float* out = (float*)d_out;

    const int smem_bytes = (3 * KK * 128 + 512) * (int)sizeof(float); // 198,656
    cudaFuncSetAttribute(gk_kernel, cudaFuncAttributeMaxDynamicSharedMemorySize,
                         smem_bytes);

    dim3 grid((MROWS + BM - 1) / BM, D1 / (BN * COLIT));  // (931, 2)
    gk_kernel<<<grid, 256, smem_bytes>>>(x, w, out);
}